// round 6
// baseline (speedup 1.0000x reference)
#include <cuda_runtime.h>
#include <cuda_bf16.h>

// GIN MessagePassing — round 5: HMMA bf16 hi/lo 3-pass, BK=64, split-K=4 on K1.
//
//   init: h0 = (1+eps)*x
//   K1:   h0 += adj@x   (split-K=4, RED.F32 combine)   M=4096 N=256 K=4096 x8
//   K2:   h1 = relu(h0@W1 + b1)                        M=32768 N=512 K=256
//   K3:   out = h1@W2 + b2                             M=32768 N=256 K=512
//
// CTA 128x256, BK=64, double-buffered (221KB smem), 8 warps, warp tile 64x64.
// A fp32 -> bf16 hi/lo in-kernel (two half-stores mid-loop); B pre-split cp.async.
// D = Ahi*Bhi + Ahi*Blo + Alo*Bhi (fp32 accum).

#define BM 128
#define BN 256
#define BK 64
#define STRD 144                       // 128B row + 16B pad (4-bank row shift)
#define A_T (128 * STRD)               // 18432
#define B_T (256 * STRD)               // 36864
#define OFF_ALO (A_T)
#define OFF_BHI (2 * A_T)
#define OFF_BLO (2 * A_T + B_T)
#define STAGE   (2 * A_T + 2 * B_T)    // 110592
#define SMEM_TOT (2 * STAGE)           // 221184

// ---------------- scratch ----------------
__device__ float g_h0[8u * 4096u * 256u];
__device__ float g_h1[8u * 4096u * 512u];
__device__ __align__(16) __nv_bfloat16 g_Bx_hi[8u * 256u * 4096u];
__device__ __align__(16) __nv_bfloat16 g_Bx_lo[8u * 256u * 4096u];
__device__ __align__(16) __nv_bfloat16 g_W1_hi[512u * 256u];
__device__ __align__(16) __nv_bfloat16 g_W1_lo[512u * 256u];
__device__ __align__(16) __nv_bfloat16 g_W2_hi[256u * 512u];
__device__ __align__(16) __nv_bfloat16 g_W2_lo[256u * 512u];

__device__ __forceinline__ unsigned s2u(const void* p) {
    unsigned a;
    asm("{ .reg .u64 t; cvta.to.shared.u64 t, %1; cvt.u32.u64 %0, t; }"
        : "=r"(a) : "l"(p));
    return a;
}
__device__ __forceinline__ void ldsm4(unsigned r[4], unsigned a) {
    asm volatile("ldmatrix.sync.aligned.m8n8.x4.shared.b16 {%0,%1,%2,%3}, [%4];"
                 : "=r"(r[0]), "=r"(r[1]), "=r"(r[2]), "=r"(r[3]) : "r"(a));
}
__device__ __forceinline__ void mma16816(float c[4], const unsigned a[4],
                                         const unsigned b[2]) {
    asm volatile(
        "mma.sync.aligned.m16n8k16.row.col.f32.bf16.bf16.f32 "
        "{%0,%1,%2,%3},{%4,%5,%6,%7},{%8,%9},{%0,%1,%2,%3};"
        : "+f"(c[0]), "+f"(c[1]), "+f"(c[2]), "+f"(c[3])
        : "r"(a[0]), "r"(a[1]), "r"(a[2]), "r"(a[3]), "r"(b[0]), "r"(b[1]));
}
__device__ __forceinline__ void cpa16(unsigned dst, const void* src) {
    asm volatile("cp.async.cg.shared.global [%0], [%1], 16;"
                 :: "r"(dst), "l"(src) : "memory");
}
__device__ __forceinline__ unsigned pack2bf(float x, float y) {
    const __nv_bfloat16 bx = __float2bfloat16(x), by = __float2bfloat16(y);
    return (unsigned)__bfloat16_as_ushort(bx) |
           ((unsigned)__bfloat16_as_ushort(by) << 16);
}

// ---------------- init: h0 = (1+eps)*x ----------------
__global__ __launch_bounds__(256)
void init_h0(const float* __restrict__ x, const float* __restrict__ epsp,
             float* __restrict__ h0, int n4)
{
    const int i = blockIdx.x * 256 + threadIdx.x;
    if (i < n4) {
        const float e = 1.0f + epsp[0];
        float4 v = ((const float4*)x)[i];
        v.x *= e; v.y *= e; v.z *= e; v.w *= e;
        ((float4*)h0)[i] = v;
    }
}

// ---------------- pack: [K,N] fp32 -> [N,K] bf16 hi/lo ----------------
__global__ __launch_bounds__(256)
void pack_bt(const float* __restrict__ in, __nv_bfloat16* __restrict__ ohi,
             __nv_bfloat16* __restrict__ olo, int K, int N)
{
    __shared__ float t[32][33];
    const int b = blockIdx.z;
    const float* ib = in + (long long)b * K * N;
    const int k0 = blockIdx.x * 32, n0 = blockIdx.y * 32;
    const int tx = threadIdx.x, ty = threadIdx.y;
#pragma unroll
    for (int i = 0; i < 4; ++i)
        t[ty + i * 8][tx] = ib[(long long)(k0 + ty + i * 8) * N + n0 + tx];
    __syncthreads();
    __nv_bfloat16* oh = ohi + (long long)b * K * N;
    __nv_bfloat16* ol = olo + (long long)b * K * N;
#pragma unroll
    for (int i = 0; i < 4; ++i) {
        const int n = n0 + ty + i * 8, k = k0 + tx;
        const float v = t[tx][ty + i * 8];
        const __nv_bfloat16 h = __float2bfloat16(v);
        const __nv_bfloat16 l = __float2bfloat16(v - __bfloat162float(h));
        oh[(long long)n * K + k] = h;
        ol[(long long)n * K + k] = l;
    }
}

// ---------------- HMMA GEMM, BK=64, optional split-K atomic epilogue ----------------
template<int EPI>   // 1: atomicAdd (K1)   2: bias+relu   3: bias
__global__ __launch_bounds__(256, 1)
void gemm2(const float* __restrict__ A,
           const __nv_bfloat16* __restrict__ Bhi,
           const __nv_bfloat16* __restrict__ Blo,
           float* __restrict__ C,
           const float* __restrict__ bias,
           int lda, int ldC, int kseg,
           long long sA, long long sB, long long sC)
{
    extern __shared__ char smem[];
    const int tid  = threadIdx.x;
    const int wid  = tid >> 5;
    const int lane = tid & 31;
    const int wm   = wid & 1;
    const int wn   = wid >> 1;

    const int zz = blockIdx.z;
    const int bz   = (EPI == 1) ? (zz >> 2) : zz;
    const int k0s  = (EPI == 1) ? (zz & 3) * kseg : 0;
    const int n0   = blockIdx.x * BN;
    const long long row0 = (long long)blockIdx.y * BM;

    const float* Ap = A + (long long)bz * sA + row0 * lda;
    const __nv_bfloat16* Bh = Bhi + (long long)bz * sB + (long long)n0 * lda;
    const __nv_bfloat16* Bl = Blo + (long long)bz * sB + (long long)n0 * lda;

    const unsigned sbase = s2u(smem);

    // A loader: 2 threads/row, half-row (32 fp32) each, split in two 16-fp32 halves
    const int ar  = tid >> 1;
    const int ac0 = (tid & 1) * 32;
    float4 pa[4];
    auto ldA = [&](int k0, int h) {
        const float* p = Ap + (long long)ar * lda + k0 + ac0 + h * 16;
        pa[0] = *(const float4*)(p);
        pa[1] = *(const float4*)(p + 4);
        pa[2] = *(const float4*)(p + 8);
        pa[3] = *(const float4*)(p + 12);
    };
    auto stA = [&](int s, int h) {
        unsigned hi[8], lo[8];
#pragma unroll
        for (int q = 0; q < 4; ++q) {
            const float f[4] = {pa[q].x, pa[q].y, pa[q].z, pa[q].w};
            float r[4];
#pragma unroll
            for (int e = 0; e < 4; ++e)
                r[e] = f[e] - __bfloat162float(__float2bfloat16(f[e]));
            hi[q * 2 + 0] = pack2bf(f[0], f[1]);
            hi[q * 2 + 1] = pack2bf(f[2], f[3]);
            lo[q * 2 + 0] = pack2bf(r[0], r[1]);
            lo[q * 2 + 1] = pack2bf(r[2], r[3]);
        }
        char* base = smem + s * STAGE;
        const unsigned off = (unsigned)(ar * STRD + ac0 * 2 + h * 32);
        *(uint4*)(base + off)                = make_uint4(hi[0], hi[1], hi[2], hi[3]);
        *(uint4*)(base + off + 16)           = make_uint4(hi[4], hi[5], hi[6], hi[7]);
        *(uint4*)(base + OFF_ALO + off)      = make_uint4(lo[0], lo[1], lo[2], lo[3]);
        *(uint4*)(base + OFF_ALO + off + 16) = make_uint4(lo[4], lo[5], lo[6], lo[7]);
    };
    // B loader: thread tid owns row tid (128B hi + 128B lo) via cp.async
    auto cpB = [&](int s, int k0) {
        const unsigned dhi = sbase + s * STAGE + OFF_BHI + tid * STRD;
        const unsigned dlo = sbase + s * STAGE + OFF_BLO + tid * STRD;
        const __nv_bfloat16* sh = Bh + (long long)tid * lda + k0;
        const __nv_bfloat16* sl = Bl + (long long)tid * lda + k0;
#pragma unroll
        for (int c = 0; c < 8; ++c) {
            cpa16(dhi + c * 16, sh + c * 8);
            cpa16(dlo + c * 16, sl + c * 8);
        }
        asm volatile("cp.async.commit_group;" ::: "memory");
    };

    // ---- prologue: fill stage 0 ----
    cpB(0, k0s);
    ldA(k0s, 0); stA(0, 0);
    ldA(k0s, 1); stA(0, 1);
    asm volatile("cp.async.wait_group 0;" ::: "memory");
    __syncthreads();

    float acc[4][8][4];
#pragma unroll
    for (int i = 0; i < 4; ++i)
#pragma unroll
        for (int j = 0; j < 8; ++j)
#pragma unroll
            for (int e = 0; e < 4; ++e) acc[i][j][e] = 0.f;

    const int lrow = lane & 7, quad = lane >> 3;
    const unsigned aoff =
        (unsigned)((wm * 64 + lrow + (quad & 1) * 8) * STRD + ((quad >> 1) * 8) * 2);
    const unsigned boff =
        (unsigned)((wn * 64 + lrow + (quad >> 1) * 8) * STRD + ((quad & 1) * 8) * 2);

    auto chunk = [&](unsigned sb, int c) {
        const unsigned kb = (unsigned)(c * 32);
        unsigned a_hi[4][4], a_lo[4][4];
#pragma unroll
        for (int i = 0; i < 4; ++i) {
            ldsm4(a_hi[i], sb + aoff + i * 16 * STRD + kb);
            ldsm4(a_lo[i], sb + OFF_ALO + aoff + i * 16 * STRD + kb);
        }
#pragma unroll
        for (int p = 0; p < 4; ++p) {
            unsigned b_hi[4], b_lo[4];
            ldsm4(b_hi, sb + OFF_BHI + boff + p * 16 * STRD + kb);
            ldsm4(b_lo, sb + OFF_BLO + boff + p * 16 * STRD + kb);
#pragma unroll
            for (int i = 0; i < 4; ++i) {
                mma16816(acc[i][2 * p + 0], a_hi[i], b_hi + 0);
                mma16816(acc[i][2 * p + 1], a_hi[i], b_hi + 2);
                mma16816(acc[i][2 * p + 0], a_hi[i], b_lo + 0);
                mma16816(acc[i][2 * p + 1], a_hi[i], b_lo + 2);
                mma16816(acc[i][2 * p + 0], a_lo[i], b_hi + 0);
                mma16816(acc[i][2 * p + 1], a_lo[i], b_hi + 2);
            }
        }
    };

    const int nIter = kseg >> 6;
    for (int it = 0; it < nIter; ++it) {
        const int s = it & 1;
        const unsigned sb = sbase + s * STAGE;
        const bool more = (it + 1 < nIter);
        const int kn = k0s + (it + 1) * 64;
        if (more) { cpB(s ^ 1, kn); ldA(kn, 0); }
        chunk(sb, 0);
        chunk(sb, 1);
        if (more) { stA(s ^ 1, 0); ldA(kn, 1); }
        chunk(sb, 2);
        chunk(sb, 3);
        if (more) {
            stA(s ^ 1, 1);
            asm volatile("cp.async.wait_group 0;" ::: "memory");
        }
        __syncthreads();
    }

    // ---- epilogue ----
    const int r4 = lane >> 2, c2 = (lane & 3) * 2;
    float* Cb = C + (long long)bz * sC;

#pragma unroll
    for (int i = 0; i < 4; ++i) {
        const long long rg0 = row0 + wm * 64 + i * 16 + r4;
#pragma unroll
        for (int j = 0; j < 8; ++j) {
            const int cg = n0 + wn * 64 + j * 8 + c2;
            if (EPI == 1) {
                atomicAdd(Cb + rg0 * ldC + cg,           acc[i][j][0]);
                atomicAdd(Cb + rg0 * ldC + cg + 1,       acc[i][j][1]);
                atomicAdd(Cb + (rg0 + 8) * ldC + cg,     acc[i][j][2]);
                atomicAdd(Cb + (rg0 + 8) * ldC + cg + 1, acc[i][j][3]);
            } else {
                float2 v0 = make_float2(acc[i][j][0], acc[i][j][1]);
                float2 v1 = make_float2(acc[i][j][2], acc[i][j][3]);
                const float bx = bias[cg], by = bias[cg + 1];
                if (EPI == 2) {
                    v0.x = fmaxf(v0.x + bx, 0.f); v0.y = fmaxf(v0.y + by, 0.f);
                    v1.x = fmaxf(v1.x + bx, 0.f); v1.y = fmaxf(v1.y + by, 0.f);
                } else {
                    v0.x += bx; v0.y += by;
                    v1.x += bx; v1.y += by;
                }
                *(float2*)(Cb + rg0 * ldC + cg)       = v0;
                *(float2*)(Cb + (rg0 + 8) * ldC + cg) = v1;
            }
        }
    }
}

extern "C" void kernel_launch(void* const* d_in, const int* in_sizes, int n_in,
                              void* d_out, int out_size)
{
    (void)in_sizes; (void)n_in; (void)out_size;
    const float* x   = (const float*)d_in[0];
    const float* adj = (const float*)d_in[1];
    const float* eps = (const float*)d_in[2];
    const float* W1  = (const float*)d_in[3];
    const float* b1  = (const float*)d_in[4];
    const float* W2  = (const float*)d_in[5];
    const float* b2  = (const float*)d_in[6];
    float* out = (float*)d_out;

    float *h0, *h1;
    __nv_bfloat16 *bxh, *bxl, *w1h, *w1l, *w2h, *w2l;
    cudaGetSymbolAddress((void**)&h0,  g_h0);
    cudaGetSymbolAddress((void**)&h1,  g_h1);
    cudaGetSymbolAddress((void**)&bxh, g_Bx_hi);
    cudaGetSymbolAddress((void**)&bxl, g_Bx_lo);
    cudaGetSymbolAddress((void**)&w1h, g_W1_hi);
    cudaGetSymbolAddress((void**)&w1l, g_W1_lo);
    cudaGetSymbolAddress((void**)&w2h, g_W2_hi);
    cudaGetSymbolAddress((void**)&w2l, g_W2_lo);

    cudaFuncSetAttribute(gemm2<1>, cudaFuncAttributeMaxDynamicSharedMemorySize, SMEM_TOT);
    cudaFuncSetAttribute(gemm2<2>, cudaFuncAttributeMaxDynamicSharedMemorySize, SMEM_TOT);
    cudaFuncSetAttribute(gemm2<3>, cudaFuncAttributeMaxDynamicSharedMemorySize, SMEM_TOT);

    // h0 = (1+eps)*x  (absorbs K1 residual; K1 accumulates via RED)
    init_h0<<<8192, 256>>>(x, eps, h0, 8 * 4096 * 256 / 4);

    const dim3 tb(32, 8);
    pack_bt<<<dim3(128, 8, 8), tb>>>(x,  bxh, bxl, 4096, 256);
    pack_bt<<<dim3(8, 16, 1),  tb>>>(W1, w1h, w1l, 256, 512);
    pack_bt<<<dim3(16, 8, 1),  tb>>>(W2, w2h, w2l, 512, 256);

    // K1: h0 += adj@x   split-K=4: z = batch*4 + split, kseg=1024
    gemm2<1><<<dim3(1, 32, 32), 256, SMEM_TOT>>>(
        adj, bxh, bxl, h0, nullptr,
        /*lda=*/4096, /*ldC=*/256, /*kseg=*/1024,
        4096LL * 4096, 256LL * 4096, 4096LL * 256);

    // K2: h1 = relu(h0@W1 + b1)
    gemm2<2><<<dim3(2, 256, 1), 256, SMEM_TOT>>>(
        h0, w1h, w1l, h1, b1,
        /*lda=*/256, /*ldC=*/512, /*kseg=*/256, 0, 0, 0);

    // K3: out = h1@W2 + b2
    gemm2<3><<<dim3(1, 256, 1), 256, SMEM_TOT>>>(
        h1, w2h, w2l, out, b2,
        /*lda=*/512, /*ldC=*/256, /*kseg=*/512, 0, 0, 0);
}

// round 8
// speedup vs baseline: 1.9600x; 1.9600x over previous
#include <cuda_runtime.h>
#include <cuda_bf16.h>

// GIN MessagePassing — round 6: HMMA bf16 hi/lo 3-pass.
// 512-thread CTA (16 warps, warp tile 32x32), BM=BN=128, BK=32,
// split-K=4 on K1 with partial buffers + deterministic reduce (no atomics).
//
//   pack:  x -> [b][256][4096] bf16 hi/lo ; W1 -> [512][256] ; W2 -> [256][512]
//   K1:   part[s] = adj[:, s-seg] @ x[s-seg]     (split-K=4)
//   red:  h0 = (1+eps)*x + sum_s part[s]
//   K2:   h1 = relu(h0@W1 + b1)
//   K3:   out = h1@W2 + b2

#define BM 128
#define BN 128
#define BK 32
#define STRD 80                      // 64B row + 16B pad, LDSM conflict-free
#define A_T (128 * STRD)             // 10240
#define B_T (128 * STRD)             // 10240
#define OFF_ALO (A_T)
#define OFF_BHI (2 * A_T)
#define OFF_BLO (2 * A_T + B_T)
#define STAGE   (2 * A_T + 2 * B_T)  // 40960
#define SMEM_TOT (2 * STAGE)         // 81920

// ---------------- scratch ----------------
__device__ float g_h0[8u * 4096u * 256u];
__device__ float g_h1[8u * 4096u * 512u];
__device__ float g_part[4u * 8u * 4096u * 256u];   // split-K partials
__device__ __align__(16) __nv_bfloat16 g_Bx_hi[8u * 256u * 4096u];
__device__ __align__(16) __nv_bfloat16 g_Bx_lo[8u * 256u * 4096u];
__device__ __align__(16) __nv_bfloat16 g_W1_hi[512u * 256u];
__device__ __align__(16) __nv_bfloat16 g_W1_lo[512u * 256u];
__device__ __align__(16) __nv_bfloat16 g_W2_hi[256u * 512u];
__device__ __align__(16) __nv_bfloat16 g_W2_lo[256u * 512u];

__device__ __forceinline__ unsigned s2u(const void* p) {
    unsigned a;
    asm("{ .reg .u64 t; cvta.to.shared.u64 t, %1; cvt.u32.u64 %0, t; }"
        : "=r"(a) : "l"(p));
    return a;
}
__device__ __forceinline__ void ldsm4(unsigned r[4], unsigned a) {
    asm volatile("ldmatrix.sync.aligned.m8n8.x4.shared.b16 {%0,%1,%2,%3}, [%4];"
                 : "=r"(r[0]), "=r"(r[1]), "=r"(r[2]), "=r"(r[3]) : "r"(a));
}
__device__ __forceinline__ void mma16816(float c[4], const unsigned a[4],
                                         const unsigned b[2]) {
    asm volatile(
        "mma.sync.aligned.m16n8k16.row.col.f32.bf16.bf16.f32 "
        "{%0,%1,%2,%3},{%4,%5,%6,%7},{%8,%9},{%0,%1,%2,%3};"
        : "+f"(c[0]), "+f"(c[1]), "+f"(c[2]), "+f"(c[3])
        : "r"(a[0]), "r"(a[1]), "r"(a[2]), "r"(a[3]), "r"(b[0]), "r"(b[1]));
}
__device__ __forceinline__ void cpa16(unsigned dst, const void* src) {
    asm volatile("cp.async.ca.shared.global [%0], [%1], 16;"
                 :: "r"(dst), "l"(src) : "memory");
}
__device__ __forceinline__ unsigned pack2bf(float x, float y) {
    const __nv_bfloat16 bx = __float2bfloat16(x), by = __float2bfloat16(y);
    return (unsigned)__bfloat16_as_ushort(bx) |
           ((unsigned)__bfloat16_as_ushort(by) << 16);
}

// ---------------- reduce: h0 = (1+eps)*x + sum of 4 partials ----------------
__global__ __launch_bounds__(256)
void reduce_h0(const float* __restrict__ x, const float* __restrict__ epsp,
               const float* __restrict__ part, float* __restrict__ h0, int n4)
{
    const int i = blockIdx.x * 256 + threadIdx.x;
    if (i >= n4) return;
    const float e = 1.0f + epsp[0];
    const long long stride = 8LL * 4096 * 256 / 4;
    float4 v = ((const float4*)x)[i];
    float4 p0 = ((const float4*)part)[i];
    float4 p1 = ((const float4*)part)[i + stride];
    float4 p2 = ((const float4*)part)[i + 2 * stride];
    float4 p3 = ((const float4*)part)[i + 3 * stride];
    float4 r;
    r.x = fmaf(e, v.x, (p0.x + p1.x) + (p2.x + p3.x));
    r.y = fmaf(e, v.y, (p0.y + p1.y) + (p2.y + p3.y));
    r.z = fmaf(e, v.z, (p0.z + p1.z) + (p2.z + p3.z));
    r.w = fmaf(e, v.w, (p0.w + p1.w) + (p2.w + p3.w));
    ((float4*)h0)[i] = r;
}

// ---------------- pack: [K,N] fp32 -> [N,K] bf16 hi/lo ----------------
__global__ __launch_bounds__(256)
void pack_bt(const float* __restrict__ in, __nv_bfloat16* __restrict__ ohi,
             __nv_bfloat16* __restrict__ olo, int K, int N)
{
    __shared__ float t[32][33];
    const int b = blockIdx.z;
    const float* ib = in + (long long)b * K * N;
    const int k0 = blockIdx.x * 32, n0 = blockIdx.y * 32;
    const int tx = threadIdx.x, ty = threadIdx.y;
#pragma unroll
    for (int i = 0; i < 4; ++i)
        t[ty + i * 8][tx] = ib[(long long)(k0 + ty + i * 8) * N + n0 + tx];
    __syncthreads();
    __nv_bfloat16* oh = ohi + (long long)b * K * N;
    __nv_bfloat16* ol = olo + (long long)b * K * N;
#pragma unroll
    for (int i = 0; i < 4; ++i) {
        const int n = n0 + ty + i * 8, k = k0 + tx;
        const float v = t[tx][ty + i * 8];
        const __nv_bfloat16 h = __float2bfloat16(v);
        const __nv_bfloat16 l = __float2bfloat16(v - __bfloat162float(h));
        oh[(long long)n * K + k] = h;
        ol[(long long)n * K + k] = l;
    }
}

// ---------------- HMMA GEMM: 512 threads, warp tile 32x32 ----------------
template<int EPI>   // 1: split-K partial store   2: bias+relu   3: bias
__global__ __launch_bounds__(512, 1)
void gemm3(const float* __restrict__ A,
           const __nv_bfloat16* __restrict__ Bhi,
           const __nv_bfloat16* __restrict__ Blo,
           float* __restrict__ C,
           const float* __restrict__ bias,
           int lda, int ldC, int kseg,
           long long sA, long long sB, long long sC)
{
    extern __shared__ char smem[];
    const int tid  = threadIdx.x;
    const int wid  = tid >> 5;
    const int lane = tid & 31;
    const int wm   = wid & 3;        // 4 warps in M (32 rows each)
    const int wn   = wid >> 2;       // 4 warps in N (32 cols each)

    const int zz  = blockIdx.z;
    const int bz  = (EPI == 1) ? (zz >> 2) : zz;
    const int sp  = (EPI == 1) ? (zz & 3) : 0;
    const int k0s = sp * kseg;
    const int n0  = blockIdx.x * BN;
    const long long row0 = (long long)blockIdx.y * BM;

    const float* Ap = A + (long long)bz * sA + row0 * lda;
    const __nv_bfloat16* Bh = Bhi + (long long)bz * sB + (long long)n0 * lda;
    const __nv_bfloat16* Bl = Blo + (long long)bz * sB + (long long)n0 * lda;

    const unsigned sbase = s2u(smem);

    // A: 128 rows x 32 fp32; thread -> row tid>>2, 8-col group (tid&3)*8
    const int ar  = tid >> 2;
    const int ac0 = (tid & 3) * 8;
    float4 pa[2];
    auto ldA = [&](int k0) {
        const float* p = Ap + (long long)ar * lda + k0 + ac0;
        pa[0] = *(const float4*)(p);
        pa[1] = *(const float4*)(p + 4);
    };
    auto stA = [&](int s) {
        const float f[8] = {pa[0].x, pa[0].y, pa[0].z, pa[0].w,
                            pa[1].x, pa[1].y, pa[1].z, pa[1].w};
        unsigned hi[4], lo[4];
#pragma unroll
        for (int q = 0; q < 4; ++q) {
            const float a = f[2 * q], b = f[2 * q + 1];
            const float ra = a - __bfloat162float(__float2bfloat16(a));
            const float rb = b - __bfloat162float(__float2bfloat16(b));
            hi[q] = pack2bf(a, b);
            lo[q] = pack2bf(ra, rb);
        }
        char* base = smem + s * STAGE;
        const unsigned off = (unsigned)(ar * STRD + ac0 * 2);
        *(uint4*)(base + off)           = make_uint4(hi[0], hi[1], hi[2], hi[3]);
        *(uint4*)(base + OFF_ALO + off) = make_uint4(lo[0], lo[1], lo[2], lo[3]);
    };
    // B: 128 rows x 32 bf16 (hi+lo); thread -> one 16B cp.async per plane
    const int br = tid >> 2;
    const int bc = tid & 3;
    auto cpB = [&](int s, int k0) {
        const unsigned d = sbase + s * STAGE + br * STRD + bc * 16;
        const long long so = (long long)br * lda + k0 + bc * 8;
        cpa16(d + OFF_BHI, Bh + so);
        cpa16(d + OFF_BLO, Bl + so);
        asm volatile("cp.async.commit_group;" ::: "memory");
    };

    // ---- prologue ----
    ldA(k0s);
    cpB(0, k0s);
    stA(0);
    asm volatile("cp.async.wait_group 0;" ::: "memory");
    __syncthreads();

    float acc[2][4][4];
#pragma unroll
    for (int i = 0; i < 2; ++i)
#pragma unroll
        for (int j = 0; j < 4; ++j)
#pragma unroll
            for (int e = 0; e < 4; ++e) acc[i][j][e] = 0.f;

    const int lrow = lane & 7, quad = lane >> 3;
    const unsigned aoff =
        (unsigned)((wm * 32 + lrow + (quad & 1) * 8) * STRD + ((quad >> 1) * 8) * 2);
    const unsigned boff =
        (unsigned)((wn * 32 + lrow + (quad >> 1) * 8) * STRD + ((quad & 1) * 8) * 2);

    const int nIter = kseg >> 5;
    for (int it = 0; it < nIter; ++it) {
        const int s = it & 1;
        const unsigned sb = sbase + s * STAGE;
        const bool more = (it + 1 < nIter);
        if (more) { ldA(k0s + (it + 1) * BK); cpB(s ^ 1, k0s + (it + 1) * BK); }

#pragma unroll
        for (int k2 = 0; k2 < 2; ++k2) {
            const unsigned kb = (unsigned)(k2 * 32);
            unsigned a_hi[2][4], a_lo[2][4];
#pragma unroll
            for (int i = 0; i < 2; ++i) {
                ldsm4(a_hi[i], sb + aoff + i * 16 * STRD + kb);
                ldsm4(a_lo[i], sb + OFF_ALO + aoff + i * 16 * STRD + kb);
            }
#pragma unroll
            for (int p = 0; p < 2; ++p) {
                unsigned b_hi[4], b_lo[4];
                ldsm4(b_hi, sb + OFF_BHI + boff + p * 16 * STRD + kb);
                ldsm4(b_lo, sb + OFF_BLO + boff + p * 16 * STRD + kb);
#pragma unroll
                for (int i = 0; i < 2; ++i) {
                    mma16816(acc[i][2 * p + 0], a_hi[i], b_hi + 0);
                    mma16816(acc[i][2 * p + 1], a_hi[i], b_hi + 2);
                    mma16816(acc[i][2 * p + 0], a_hi[i], b_lo + 0);
                    mma16816(acc[i][2 * p + 1], a_hi[i], b_lo + 2);
                    mma16816(acc[i][2 * p + 0], a_lo[i], b_hi + 0);
                    mma16816(acc[i][2 * p + 1], a_lo[i], b_hi + 2);
                }
            }
        }
        if (more) {
            stA(s ^ 1);
            asm volatile("cp.async.wait_group 0;" ::: "memory");
        }
        __syncthreads();
    }

    // ---- epilogue ----
    const int r4 = lane >> 2, c2 = (lane & 3) * 2;
    float* Cb = C + (long long)((EPI == 1) ? (sp * 8 + bz) : bz) * sC;

#pragma unroll
    for (int i = 0; i < 2; ++i) {
        const long long rg0 = row0 + wm * 32 + i * 16 + r4;
#pragma unroll
        for (int j = 0; j < 4; ++j) {
            const int cg = n0 + wn * 32 + j * 8 + c2;
            float2 v0 = make_float2(acc[i][j][0], acc[i][j][1]);
            float2 v1 = make_float2(acc[i][j][2], acc[i][j][3]);
            if (EPI == 2) {
                const float bx = bias[cg], by = bias[cg + 1];
                v0.x = fmaxf(v0.x + bx, 0.f); v0.y = fmaxf(v0.y + by, 0.f);
                v1.x = fmaxf(v1.x + bx, 0.f); v1.y = fmaxf(v1.y + by, 0.f);
            } else if (EPI == 3) {
                const float bx = bias[cg], by = bias[cg + 1];
                v0.x += bx; v0.y += by;
                v1.x += bx; v1.y += by;
            }
            *(float2*)(Cb + rg0 * ldC + cg)       = v0;
            *(float2*)(Cb + (rg0 + 8) * ldC + cg) = v1;
        }
    }
}

extern "C" void kernel_launch(void* const* d_in, const int* in_sizes, int n_in,
                              void* d_out, int out_size)
{
    (void)in_sizes; (void)n_in; (void)out_size;
    const float* x   = (const float*)d_in[0];
    const float* adj = (const float*)d_in[1];
    const float* eps = (const float*)d_in[2];
    const float* W1  = (const float*)d_in[3];
    const float* b1  = (const float*)d_in[4];
    const float* W2  = (const float*)d_in[5];
    const float* b2  = (const float*)d_in[6];
    float* out = (float*)d_out;

    float *h0, *h1, *part;
    __nv_bfloat16 *bxh, *bxl, *w1h, *w1l, *w2h, *w2l;
    cudaGetSymbolAddress((void**)&h0,   g_h0);
    cudaGetSymbolAddress((void**)&h1,   g_h1);
    cudaGetSymbolAddress((void**)&part, g_part);
    cudaGetSymbolAddress((void**)&bxh,  g_Bx_hi);
    cudaGetSymbolAddress((void**)&bxl,  g_Bx_lo);
    cudaGetSymbolAddress((void**)&w1h,  g_W1_hi);
    cudaGetSymbolAddress((void**)&w1l,  g_W1_lo);
    cudaGetSymbolAddress((void**)&w2h,  g_W2_hi);
    cudaGetSymbolAddress((void**)&w2l,  g_W2_lo);

    cudaFuncSetAttribute(gemm3<1>, cudaFuncAttributeMaxDynamicSharedMemorySize, SMEM_TOT);
    cudaFuncSetAttribute(gemm3<2>, cudaFuncAttributeMaxDynamicSharedMemorySize, SMEM_TOT);
    cudaFuncSetAttribute(gemm3<3>, cudaFuncAttributeMaxDynamicSharedMemorySize, SMEM_TOT);

    const dim3 tb(32, 8);
    pack_bt<<<dim3(128, 8, 8), tb>>>(x,  bxh, bxl, 4096, 256);
    pack_bt<<<dim3(8, 16, 1),  tb>>>(W1, w1h, w1l, 256, 512);
    pack_bt<<<dim3(16, 8, 1),  tb>>>(W2, w2h, w2l, 512, 256);

    // K1: part[sp][b] = adj[b][:, sp-seg] @ x[b][sp-seg]   (z = b*4 + sp)
    gemm3<1><<<dim3(2, 32, 32), 512, SMEM_TOT>>>(
        adj, bxh, bxl, part, nullptr,
        /*lda=*/4096, /*ldC=*/256, /*kseg=*/1024,
        4096LL * 4096, 256LL * 4096, 4096LL * 256);

    // reduce: h0 = (1+eps)*x + sum partials
    reduce_h0<<<8192, 256>>>(x, eps, part, h0, 8 * 4096 * 256 / 4);

    // K2: h1 = relu(h0@W1 + b1)    grid (512/128=4, 32768/128=256)
    gemm3<2><<<dim3(4, 256, 1), 512, SMEM_TOT>>>(
        h0, w1h, w1l, h1, b1,
        /*lda=*/256, /*ldC=*/512, /*kseg=*/256, 0, 0, 0);

    // K3: out = h1@W2 + b2         grid (2, 256)
    gemm3<3><<<dim3(2, 256, 1), 512, SMEM_TOT>>>(
        h1, w2h, w2l, out, b2,
        /*lda=*/512, /*ldC=*/256, /*kseg=*/512, 0, 0, 0);
}